// round 11
// baseline (speedup 1.0000x reference)
#include <cuda_runtime.h>
#include <cstdint>

// ----------------------------------------------------------------------------
// Fused sparse conv on the tensor pipe. Per block = 128 pairs of one offset k.
//   one memory phase: stage W hi/lo (interleaved) + pair recs + RAW x -> smem
//   -> mma.sync.m16n8k8 tf32 3xTF32, balanced warp tiles (2x4 / 2x2)
//   -> red.global.add.v2.f32 DIRECTLY from accumulators (no C staging).
// ----------------------------------------------------------------------------

constexpr int CIN   = 32;
constexpr int CMID  = 64;
constexpr int COUT  = 32;
constexpr int MAXK  = 27;
constexpr int MAXP  = 400000;
constexpr int MAXN  = 200192;
constexpr int PT    = 128;       // pairs per block

// x strides (floats): 36/68 -> (4r+c) covers 32 banks for fragment loads.
constexpr int SX1 = 36;
constexpr int SX2 = 68;
// interleaved W strides (floats, hi/lo pairs): ≡8 mod 32 -> conflict-free LDS.64
constexpr int SWI1 = 136;   // >= 2*CMID, 136 % 32 == 8
constexpr int SWI2 = 72;    // >= 2*COUT,  72 % 32 == 8

constexpr int POOL1F = PT * SX1 + CIN  * SWI1;   //  8960 f = 35 KB
constexpr int POOL2F = PT * SX2 + CMID * SWI2;   // 13312 f = 52 KB

__device__ float g_h[(size_t)MAXN * CMID];
__device__ uint2 g_pairs[(size_t)MAXK * MAXP];
__device__ int   g_cnt[MAXK];

static __device__ __forceinline__ unsigned f2tf(float x) {
    unsigned r; asm("cvt.rna.tf32.f32 %0, %1;" : "=r"(r) : "f"(x)); return r;
}
static __device__ __forceinline__ void hilo_u(float x, unsigned& h, unsigned& l) {
    h = f2tf(x);
    l = f2tf(x - __uint_as_float(h));
}
static __device__ __forceinline__ void mma_tf32(
    float4& c, unsigned a0, unsigned a1, unsigned a2, unsigned a3,
    unsigned b0, unsigned b1)
{
    asm volatile(
        "mma.sync.aligned.m16n8k8.row.col.f32.tf32.tf32.f32 "
        "{%0,%1,%2,%3}, {%4,%5,%6,%7}, {%8,%9}, {%0,%1,%2,%3};"
        : "+f"(c.x), "+f"(c.y), "+f"(c.z), "+f"(c.w)
        : "r"(a0), "r"(a1), "r"(a2), "r"(a3), "r"(b0), "r"(b1));
}
static __device__ __forceinline__ void red_add_v2(float* p, float x, float y) {
    asm volatile("red.global.add.v2.f32 [%0], {%1, %2};"
                 :: "l"(p), "f"(x), "f"(y) : "memory");
}

// ---------------------------------------------------------------------------
__global__ void zero_kernel(float4* __restrict__ out, int n_out4, int n_h4) {
    int i = blockIdx.x * blockDim.x + threadIdx.x;
    float4 z = make_float4(0.f, 0.f, 0.f, 0.f);
    if (i < n_out4) out[i] = z;
    if (i < n_h4) reinterpret_cast<float4*>(g_h)[i] = z;
    if (i < MAXK) g_cnt[i] = 0;
}

// ---------------------------------------------------------------------------
__global__ __launch_bounds__(256) void compact_kernel(
    const int* __restrict__ in_idx, const int* __restrict__ out_idx,
    const float* __restrict__ mask, int P)
{
    const int k = blockIdx.y;
    const int p = blockIdx.x * blockDim.x + threadIdx.x;
    bool v = false; int vin = 0, vout = 0;
    if (p < P) {
        size_t o = (size_t)k * P + p;
        v = mask[o] > 0.5f;
        if (v) { vin = in_idx[o]; vout = out_idx[o]; }
    }
    unsigned b = __ballot_sync(0xffffffffu, v);
    int cnt = __popc(b);
    if (cnt == 0) return;
    const int lane = threadIdx.x & 31;
    const int leader = __ffs(b) - 1;
    int base = 0;
    if (lane == leader) base = atomicAdd(&g_cnt[k], cnt);
    base = __shfl_sync(0xffffffffu, base, leader);
    if (v) {
        int off = __popc(b & ((1u << lane) - 1u));
        g_pairs[(size_t)k * MAXP + base + off] =
            make_uint2((unsigned)vin, (unsigned)vout);
    }
}

// ---------------------------------------------------------------------------
// Fused layer 1: g_h[vout][0:64] += feats[vin][0:32] @ W_in[k]
// Warp tile: MT=2 (rows 32*(w&3), +16), NT=4 (cols 32*(w>>2), 8 each). K=32.
// ---------------------------------------------------------------------------
__global__ __launch_bounds__(256) void fused1_kernel(
    const float* __restrict__ feats, const float* __restrict__ W_in)
{
    const int k    = blockIdx.y;
    const int cnt  = g_cnt[k];
    const int base = blockIdx.x * PT;
    if (base >= cnt) return;
    const int t    = threadIdx.x;
    const int lane = t & 31;
    const int wrp  = t >> 5;
    const int nv   = min(PT, cnt - base);

    extern __shared__ float pool[];
    float* sx  = pool;                   // [PT][SX1] raw x
    float* swi = pool + PT * SX1;        // [CIN][SWI1] interleaved (hi,lo)
    __shared__ uint2 sp[PT];

    // ---- single memory phase ----
    {
        const int r = t >> 1, half = t & 1;
        uint2 pr = (r < nv) ? g_pairs[(size_t)k * MAXP + base + r]
                            : make_uint2(0u, 0u);
        if (half == 0) sp[r] = pr;
        const float4* src = reinterpret_cast<const float4*>(feats + (size_t)pr.x * CIN);
        float* drow = sx + r * SX1;
#pragma unroll
        for (int q = 0; q < 4; q++) {
            float4 v = src[half * 4 + q];
            float* d = drow + (half * 4 + q) * 4;
            d[0] = v.x; d[1] = v.y; d[2] = v.z; d[3] = v.w;
        }
    }
    for (int i = t; i < CIN * CMID; i += 256) {
        int c = i >> 6, d = i & 63;
        unsigned h, l; hilo_u(W_in[(size_t)k * CIN * CMID + i], h, l);
        reinterpret_cast<float2*>(swi + c * SWI1)[d] =
            make_float2(__uint_as_float(h), __uint_as_float(l));
    }
    __syncthreads();

    const int gid = lane >> 2, tig = lane & 3;
    const int rbase = 32 * (wrp & 3);          // row block (two m-tiles)
    const int cbase = 32 * (wrp >> 2);         // col block (four n-tiles)

    float4 acc[2][4];
#pragma unroll
    for (int mt = 0; mt < 2; mt++)
#pragma unroll
        for (int nt = 0; nt < 4; nt++) acc[mt][nt] = make_float4(0.f, 0.f, 0.f, 0.f);

#pragma unroll
    for (int ks = 0; ks < 4; ks++) {
        const int ka = ks * 8;
        unsigned ah[2][4], al[2][4];
#pragma unroll
        for (int mt = 0; mt < 2; mt++) {
            const int r0 = rbase + mt * 16 + gid;
            hilo_u(sx[r0 * SX1 + ka + tig],           ah[mt][0], al[mt][0]);
            hilo_u(sx[(r0 + 8) * SX1 + ka + tig],     ah[mt][1], al[mt][1]);
            hilo_u(sx[r0 * SX1 + ka + tig + 4],       ah[mt][2], al[mt][2]);
            hilo_u(sx[(r0 + 8) * SX1 + ka + tig + 4], ah[mt][3], al[mt][3]);
        }
#pragma unroll
        for (int nt = 0; nt < 4; nt++) {
            const int nc = cbase + nt * 8 + gid;
            float2 b0 = reinterpret_cast<const float2*>(swi + (ka + tig) * SWI1)[nc];
            float2 b1 = reinterpret_cast<const float2*>(swi + (ka + tig + 4) * SWI1)[nc];
            unsigned bh0 = __float_as_uint(b0.x), bl0 = __float_as_uint(b0.y);
            unsigned bh1 = __float_as_uint(b1.x), bl1 = __float_as_uint(b1.y);
#pragma unroll
            for (int mt = 0; mt < 2; mt++) {
                mma_tf32(acc[mt][nt], ah[mt][0], ah[mt][1], ah[mt][2], ah[mt][3], bh0, bh1);
                mma_tf32(acc[mt][nt], ah[mt][0], ah[mt][1], ah[mt][2], ah[mt][3], bl0, bl1);
                mma_tf32(acc[mt][nt], al[mt][0], al[mt][1], al[mt][2], al[mt][3], bh0, bh1);
            }
        }
    }

    // ---- scatter directly from accumulators (red.v2) ----
#pragma unroll
    for (int mt = 0; mt < 2; mt++) {
        const int r0 = rbase + mt * 16 + gid;
#pragma unroll
        for (int nt = 0; nt < 4; nt++) {
            const int cc = cbase + nt * 8 + 2 * tig;
            if (r0 < nv)
                red_add_v2(g_h + (size_t)sp[r0].y * CMID + cc,
                           acc[mt][nt].x, acc[mt][nt].y);
            if (r0 + 8 < nv)
                red_add_v2(g_h + (size_t)sp[r0 + 8].y * CMID + cc,
                           acc[mt][nt].z, acc[mt][nt].w);
        }
    }
}

// ---------------------------------------------------------------------------
// Fused layer 2: out[vout][0:32] += relu(g_h[vin][0:64]) @ W_out[k]
// Warp tile: MT=2 (rows 32*(w&3)), NT=2 (cols 16*(w>>2)). K=64.
// ---------------------------------------------------------------------------
__global__ __launch_bounds__(256) void fused2_kernel(
    const float* __restrict__ W_out, float* __restrict__ out)
{
    const int k    = blockIdx.y;
    const int cnt  = g_cnt[k];
    const int base = blockIdx.x * PT;
    if (base >= cnt) return;
    const int t    = threadIdx.x;
    const int lane = t & 31;
    const int wrp  = t >> 5;
    const int nv   = min(PT, cnt - base);

    extern __shared__ float pool[];
    float* sx  = pool;                   // [PT][SX2] raw relu(h)
    float* swi = pool + PT * SX2;        // [CMID][SWI2] interleaved (hi,lo)
    __shared__ uint2 sp[PT];

    // ---- single memory phase ----
    {
        const int r = t >> 1, half = t & 1;
        uint2 pr = (r < nv) ? g_pairs[(size_t)k * MAXP + base + r]
                            : make_uint2(0u, 0u);
        if (half == 0) sp[r] = pr;
        const float4* src = reinterpret_cast<const float4*>(g_h + (size_t)pr.x * CMID);
        float* drow = sx + r * SX2;
#pragma unroll
        for (int q = 0; q < 8; q++) {
            float4 v = src[half * 8 + q];
            float* d = drow + (half * 8 + q) * 4;
            d[0] = fmaxf(v.x, 0.f); d[1] = fmaxf(v.y, 0.f);
            d[2] = fmaxf(v.z, 0.f); d[3] = fmaxf(v.w, 0.f);
        }
    }
    for (int i = t; i < CMID * COUT; i += 256) {
        int c = i >> 5, d = i & 31;
        unsigned h, l; hilo_u(W_out[(size_t)k * CMID * COUT + i], h, l);
        reinterpret_cast<float2*>(swi + c * SWI2)[d] =
            make_float2(__uint_as_float(h), __uint_as_float(l));
    }
    __syncthreads();

    const int gid = lane >> 2, tig = lane & 3;
    const int rbase = 32 * (wrp & 3);
    const int cbase = 16 * (wrp >> 2);

    float4 acc[2][2];
#pragma unroll
    for (int mt = 0; mt < 2; mt++)
#pragma unroll
        for (int nt = 0; nt < 2; nt++) acc[mt][nt] = make_float4(0.f, 0.f, 0.f, 0.f);

#pragma unroll
    for (int ks = 0; ks < 8; ks++) {
        const int ka = ks * 8;
        unsigned ah[2][4], al[2][4];
#pragma unroll
        for (int mt = 0; mt < 2; mt++) {
            const int r0 = rbase + mt * 16 + gid;
            hilo_u(sx[r0 * SX2 + ka + tig],           ah[mt][0], al[mt][0]);
            hilo_u(sx[(r0 + 8) * SX2 + ka + tig],     ah[mt][1], al[mt][1]);
            hilo_u(sx[r0 * SX2 + ka + tig + 4],       ah[mt][2], al[mt][2]);
            hilo_u(sx[(r0 + 8) * SX2 + ka + tig + 4], ah[mt][3], al[mt][3]);
        }
#pragma unroll
        for (int nt = 0; nt < 2; nt++) {
            const int nc = cbase + nt * 8 + gid;
            float2 b0 = reinterpret_cast<const float2*>(swi + (ka + tig) * SWI2)[nc];
            float2 b1 = reinterpret_cast<const float2*>(swi + (ka + tig + 4) * SWI2)[nc];
            unsigned bh0 = __float_as_uint(b0.x), bl0 = __float_as_uint(b0.y);
            unsigned bh1 = __float_as_uint(b1.x), bl1 = __float_as_uint(b1.y);
#pragma unroll
            for (int mt = 0; mt < 2; mt++) {
                mma_tf32(acc[mt][nt], ah[mt][0], ah[mt][1], ah[mt][2], ah[mt][3], bh0, bh1);
                mma_tf32(acc[mt][nt], ah[mt][0], ah[mt][1], ah[mt][2], ah[mt][3], bl0, bl1);
                mma_tf32(acc[mt][nt], al[mt][0], al[mt][1], al[mt][2], al[mt][3], bh0, bh1);
            }
        }
    }

    // ---- scatter directly from accumulators ----
#pragma unroll
    for (int mt = 0; mt < 2; mt++) {
        const int r0 = rbase + mt * 16 + gid;
#pragma unroll
        for (int nt = 0; nt < 2; nt++) {
            const int cc = cbase + nt * 8 + 2 * tig;
            if (r0 < nv)
                red_add_v2(out + (size_t)sp[r0].y * COUT + cc,
                           acc[mt][nt].x, acc[mt][nt].y);
            if (r0 + 8 < nv)
                red_add_v2(out + (size_t)sp[r0 + 8].y * COUT + cc,
                           acc[mt][nt].z, acc[mt][nt].w);
        }
    }
}

// ---------------------------------------------------------------------------
// Inputs: feats f32[N,32], nbr_in_idx i32[K,P], nbr_out_idx i32[K,P],
// nbr_mask f32[K,P], W_in f32[K,32,64], W_out f32[K,64,32]. Output f32[N,32].
// ---------------------------------------------------------------------------
extern "C" void kernel_launch(void* const* d_in, const int* in_sizes, int n_in,
                              void* d_out, int out_size) {
    const float* feats   = (const float*)d_in[0];
    const int*   in_idx  = (const int*)  d_in[1];
    const int*   out_idx = (const int*)  d_in[2];
    const float* mask    = (const float*)d_in[3];
    const float* W_in    = (const float*)d_in[4];
    const float* W_out   = (const float*)d_in[5];
    float*       out     = (float*)      d_out;

    const int N = in_sizes[0] / CIN;
    const int K = in_sizes[4] / (CIN * CMID);
    const int P = in_sizes[3] / K;

    const int smem1 = POOL1F * (int)sizeof(float);   // 35 KB
    const int smem2 = POOL2F * (int)sizeof(float);   // 52 KB
    cudaFuncSetAttribute(fused1_kernel,
        cudaFuncAttributeMaxDynamicSharedMemorySize, smem1);
    cudaFuncSetAttribute(fused2_kernel,
        cudaFuncAttributeMaxDynamicSharedMemorySize, smem2);

    const int n_out4 = N * COUT / 4;
    const int n_h4   = N * CMID / 4;
    const int nmax   = (n_out4 > n_h4) ? n_out4 : n_h4;
    zero_kernel<<<(nmax + 255) / 256, 256>>>((float4*)out, n_out4, n_h4);

    dim3 gc((P + 255) / 256, K);
    compact_kernel<<<gc, 256>>>(in_idx, out_idx, mask, P);

    dim3 gf((P + PT - 1) / PT, K);
    fused1_kernel<<<gf, 256, smem1>>>(feats, W_in);
    fused2_kernel<<<gf, 256, smem2>>>(W_out, out);
}

// round 12
// speedup vs baseline: 1.0407x; 1.0407x over previous
#include <cuda_runtime.h>
#include <cstdint>

// ----------------------------------------------------------------------------
// Fused sparse conv on the tensor pipe. Block = up to 4 tiles of 128 pairs of
// one offset k (W staged once per block from PRECOMPUTED tf32 hi/lo planes).
//   gather x -> paired-layout smem (A-frags = LDS.64) -> m16n8k8 tf32 3xTF32
//   -> red.global.add.v2 straight from accumulators.
// ----------------------------------------------------------------------------

constexpr int CIN   = 32;
constexpr int CMID  = 64;
constexpr int COUT  = 32;
constexpr int MAXK  = 27;
constexpr int MAXP  = 400000;
constexpr int MAXN  = 200192;
constexpr int PT    = 128;       // pairs per tile
constexpr int TILES = 4;         // tiles per block (bounded loop)

// x staged as float2 pairs (x[c], x[c+4]); row stride in float2 units,
// 2*SXP % 32 == 8 -> conflict-free LDS.64 per 16-lane phase.
constexpr int SXP1 = 20;   // layer1: 16 slots + pad
constexpr int SXP2 = 36;   // layer2: 32 slots + pad
// interleaved W strides (floats): ≡8 mod 32 -> conflict-free LDS.64
constexpr int SWI1 = 136;
constexpr int SWI2 = 72;

constexpr int POOL1F = PT * SXP1 * 2 + CIN  * SWI1;  //  9472 f = 37 KB
constexpr int POOL2F = PT * SXP2 * 2 + CMID * SWI2;  // 13824 f = 54 KB

__device__ float  g_h[(size_t)MAXN * CMID];
__device__ uint2  g_pairs[(size_t)MAXK * MAXP];
__device__ int    g_cnt[MAXK];
__device__ float2 g_wp1[(size_t)MAXK * CIN * CMID];   // W_in  tf32 (hi,lo)
__device__ float2 g_wp2[(size_t)MAXK * CMID * COUT];  // W_out tf32 (hi,lo)

static __device__ __forceinline__ unsigned f2tf(float x) {
    unsigned r; asm("cvt.rna.tf32.f32 %0, %1;" : "=r"(r) : "f"(x)); return r;
}
static __device__ __forceinline__ void hilo_u(float x, unsigned& h, unsigned& l) {
    h = f2tf(x);
    l = f2tf(x - __uint_as_float(h));
}
static __device__ __forceinline__ void mma_tf32(
    float4& c, unsigned a0, unsigned a1, unsigned a2, unsigned a3,
    unsigned b0, unsigned b1)
{
    asm volatile(
        "mma.sync.aligned.m16n8k8.row.col.f32.tf32.tf32.f32 "
        "{%0,%1,%2,%3}, {%4,%5,%6,%7}, {%8,%9}, {%0,%1,%2,%3};"
        : "+f"(c.x), "+f"(c.y), "+f"(c.z), "+f"(c.w)
        : "r"(a0), "r"(a1), "r"(a2), "r"(a3), "r"(b0), "r"(b1));
}
static __device__ __forceinline__ void red_add_v2(float* p, float x, float y) {
    asm volatile("red.global.add.v2.f32 [%0], {%1, %2};"
                 :: "l"(p), "f"(x), "f"(y) : "memory");
}

// ---------------------------------------------------------------------------
__global__ void zero_kernel(float4* __restrict__ out, int n_out4, int n_h4) {
    int i = blockIdx.x * blockDim.x + threadIdx.x;
    float4 z = make_float4(0.f, 0.f, 0.f, 0.f);
    if (i < n_out4) out[i] = z;
    if (i < n_h4) reinterpret_cast<float4*>(g_h)[i] = z;
    if (i < MAXK) g_cnt[i] = 0;
}

// ---------------------------------------------------------------------------
// Precompute tf32 hi/lo planes for both weight tensors.
// ---------------------------------------------------------------------------
__global__ void wprep_kernel(const float* __restrict__ W_in,
                             const float* __restrict__ W_out, int K) {
    int i = blockIdx.x * blockDim.x + threadIdx.x;
    int tot1 = K * CIN * CMID;
    int tot2 = K * CMID * COUT;
    if (i < tot1) {
        unsigned h, l; hilo_u(W_in[i], h, l);
        g_wp1[i] = make_float2(__uint_as_float(h), __uint_as_float(l));
    }
    if (i < tot2) {
        unsigned h, l; hilo_u(W_out[i], h, l);
        g_wp2[i] = make_float2(__uint_as_float(h), __uint_as_float(l));
    }
}

// ---------------------------------------------------------------------------
__global__ __launch_bounds__(256) void compact_kernel(
    const int* __restrict__ in_idx, const int* __restrict__ out_idx,
    const float* __restrict__ mask, int P)
{
    const int k = blockIdx.y;
    const int p = blockIdx.x * blockDim.x + threadIdx.x;
    bool v = false; int vin = 0, vout = 0;
    if (p < P) {
        size_t o = (size_t)k * P + p;
        v = mask[o] > 0.5f;
        if (v) { vin = in_idx[o]; vout = out_idx[o]; }
    }
    unsigned b = __ballot_sync(0xffffffffu, v);
    int cnt = __popc(b);
    if (cnt == 0) return;
    const int lane = threadIdx.x & 31;
    const int leader = __ffs(b) - 1;
    int base = 0;
    if (lane == leader) base = atomicAdd(&g_cnt[k], cnt);
    base = __shfl_sync(0xffffffffu, base, leader);
    if (v) {
        int off = __popc(b & ((1u << lane) - 1u));
        g_pairs[(size_t)k * MAXP + base + off] =
            make_uint2((unsigned)vin, (unsigned)vout);
    }
}

// ---------------------------------------------------------------------------
// Fused layer 1: g_h[vout][0:64] += feats[vin][0:32] @ W_in[k]
// Warp tile MT=2 (rows 32*(w&3)), NT=4 (cols 32*(w>>2)). K=32 (4 ks).
// ---------------------------------------------------------------------------
__global__ __launch_bounds__(256) void fused1_kernel(
    const float* __restrict__ feats)
{
    const int k    = blockIdx.y;
    const int cnt  = g_cnt[k];
    const int t    = threadIdx.x;
    const int lane = t & 31;
    const int wrp  = t >> 5;

    extern __shared__ float pool[];
    float2* sxp = reinterpret_cast<float2*>(pool);        // [PT][SXP1]
    float*  swi = pool + 2 * PT * SXP1;                   // [CIN][SWI1]
    __shared__ uint2 sp[PT];

    // Stage W (pure float2 copy) once per block.
    {
        const float2* src = g_wp1 + (size_t)k * CIN * CMID;
        for (int i = t; i < CIN * CMID; i += 256) {
            int c = i >> 6, d = i & 63;
            *reinterpret_cast<float2*>(swi + c * SWI1 + 2 * d) = src[i];
        }
    }

    const int gid = lane >> 2, tig = lane & 3;
    const int rbase = 32 * (wrp & 3);
    const int cbase = 32 * (wrp >> 2);
    const float2* a0p = sxp + (rbase + gid) * SXP1;
    const float2* a1p = a0p + 8 * SXP1;
    const float2* a2p = a0p + 16 * SXP1;
    const float2* a3p = a0p + 24 * SXP1;

    for (int tile = blockIdx.x; tile * PT < cnt; tile += gridDim.x) {
        const int base = tile * PT;
        const int nv   = min(PT, cnt - base);

        // ---- gather: pair recs + x rows in paired layout ----
        {
            const int r = t >> 1, half = t & 1;
            uint2 pr = (r < nv) ? g_pairs[(size_t)k * MAXP + base + r]
                                : make_uint2(0u, 0u);
            if (half == 0) sp[r] = pr;
            const float4* src = reinterpret_cast<const float4*>(feats + (size_t)pr.x * CIN);
            float4* drow = reinterpret_cast<float4*>(sxp + r * SXP1);
#pragma unroll
            for (int b = 0; b < 2; b++) {           // 8-blocks 2*half+b
                const int ab = 2 * half + b;
                float4 va = src[2 * ab], vb = src[2 * ab + 1];
                drow[ab * 2]     = make_float4(va.x, vb.x, va.y, vb.y);
                drow[ab * 2 + 1] = make_float4(va.z, vb.z, va.w, vb.w);
            }
        }
        __syncthreads();

        float4 acc[2][4];
#pragma unroll
        for (int mt = 0; mt < 2; mt++)
#pragma unroll
            for (int nt = 0; nt < 4; nt++) acc[mt][nt] = make_float4(0.f, 0.f, 0.f, 0.f);

#pragma unroll
        for (int ks = 0; ks < 4; ks++) {
            const int s = ks * 4 + tig;
            float2 p00 = a0p[s], p01 = a1p[s];      // mt=0: rows r0, r0+8
            float2 p10 = a2p[s], p11 = a3p[s];      // mt=1
            unsigned ah[2][4], al[2][4];
            hilo_u(p00.x, ah[0][0], al[0][0]); hilo_u(p01.x, ah[0][1], al[0][1]);
            hilo_u(p00.y, ah[0][2], al[0][2]); hilo_u(p01.y, ah[0][3], al[0][3]);
            hilo_u(p10.x, ah[1][0], al[1][0]); hilo_u(p11.x, ah[1][1], al[1][1]);
            hilo_u(p10.y, ah[1][2], al[1][2]); hilo_u(p11.y, ah[1][3], al[1][3]);
            const int ka = ks * 8;
#pragma unroll
            for (int nt = 0; nt < 4; nt++) {
                const int nc = cbase + nt * 8 + gid;
                float2 b0 = *reinterpret_cast<const float2*>(swi + (ka + tig) * SWI1 + 2 * nc);
                float2 b1 = *reinterpret_cast<const float2*>(swi + (ka + tig + 4) * SWI1 + 2 * nc);
                unsigned bh0 = __float_as_uint(b0.x), bl0 = __float_as_uint(b0.y);
                unsigned bh1 = __float_as_uint(b1.x), bl1 = __float_as_uint(b1.y);
#pragma unroll
                for (int mt = 0; mt < 2; mt++) {
                    mma_tf32(acc[mt][nt], ah[mt][0], ah[mt][1], ah[mt][2], ah[mt][3], bh0, bh1);
                    mma_tf32(acc[mt][nt], ah[mt][0], ah[mt][1], ah[mt][2], ah[mt][3], bl0, bl1);
                    mma_tf32(acc[mt][nt], al[mt][0], al[mt][1], al[mt][2], al[mt][3], bh0, bh1);
                }
            }
        }

        // ---- scatter from accumulators (reads sp, no sx access) ----
#pragma unroll
        for (int mt = 0; mt < 2; mt++) {
            const int r0 = rbase + mt * 16 + gid;
#pragma unroll
            for (int nt = 0; nt < 4; nt++) {
                const int cc = cbase + nt * 8 + 2 * tig;
                if (r0 < nv)
                    red_add_v2(g_h + (size_t)sp[r0].y * CMID + cc,
                               acc[mt][nt].x, acc[mt][nt].y);
                if (r0 + 8 < nv)
                    red_add_v2(g_h + (size_t)sp[r0 + 8].y * CMID + cc,
                               acc[mt][nt].z, acc[mt][nt].w);
            }
        }
        __syncthreads();   // sp/sx free for next tile
    }
}

// ---------------------------------------------------------------------------
// Fused layer 2: out[vout][0:32] += relu(g_h[vin][0:64]) @ W_out[k]
// Warp tile MT=2 (rows 32*(w&3)), NT=2 (cols 16*(w>>2)). K=64 (8 ks).
// ---------------------------------------------------------------------------
__global__ __launch_bounds__(256) void fused2_kernel(float* __restrict__ out)
{
    const int k    = blockIdx.y;
    const int cnt  = g_cnt[k];
    const int t    = threadIdx.x;
    const int lane = t & 31;
    const int wrp  = t >> 5;

    extern __shared__ float pool[];
    float2* sxp = reinterpret_cast<float2*>(pool);        // [PT][SXP2]
    float*  swi = pool + 2 * PT * SXP2;                   // [CMID][SWI2]
    __shared__ uint2 sp[PT];

    {
        const float2* src = g_wp2 + (size_t)k * CMID * COUT;
        for (int i = t; i < CMID * COUT; i += 256) {
            int c = i >> 5, d = i & 31;
            *reinterpret_cast<float2*>(swi + c * SWI2 + 2 * d) = src[i];
        }
    }

    const int gid = lane >> 2, tig = lane & 3;
    const int rbase = 32 * (wrp & 3);
    const int cbase = 16 * (wrp >> 2);
    const float2* a0p = sxp + (rbase + gid) * SXP2;
    const float2* a1p = a0p + 8 * SXP2;
    const float2* a2p = a0p + 16 * SXP2;
    const float2* a3p = a0p + 24 * SXP2;

    for (int tile = blockIdx.x; tile * PT < cnt; tile += gridDim.x) {
        const int base = tile * PT;
        const int nv   = min(PT, cnt - base);

        // ---- gather: pair recs + relu(h) rows in paired layout ----
        {
            const int r = t >> 1, half = t & 1;
            uint2 pr = (r < nv) ? g_pairs[(size_t)k * MAXP + base + r]
                                : make_uint2(0u, 0u);
            if (half == 0) sp[r] = pr;
            const float4* src = reinterpret_cast<const float4*>(g_h + (size_t)pr.x * CMID);
            float4* drow = reinterpret_cast<float4*>(sxp + r * SXP2);
#pragma unroll
            for (int b = 0; b < 4; b++) {           // 8-blocks 4*half+b
                const int ab = 4 * half + b;
                float4 va = src[2 * ab], vb = src[2 * ab + 1];
                va.x = fmaxf(va.x, 0.f); va.y = fmaxf(va.y, 0.f);
                va.z = fmaxf(va.z, 0.f); va.w = fmaxf(va.w, 0.f);
                vb.x = fmaxf(vb.x, 0.f); vb.y = fmaxf(vb.y, 0.f);
                vb.z = fmaxf(vb.z, 0.f); vb.w = fmaxf(vb.w, 0.f);
                drow[ab * 2]     = make_float4(va.x, vb.x, va.y, vb.y);
                drow[ab * 2 + 1] = make_float4(va.z, vb.z, va.w, vb.w);
            }
        }
        __syncthreads();

        float4 acc[2][2];
#pragma unroll
        for (int mt = 0; mt < 2; mt++)
#pragma unroll
            for (int nt = 0; nt < 2; nt++) acc[mt][nt] = make_float4(0.f, 0.f, 0.f, 0.f);

#pragma unroll
        for (int ks = 0; ks < 8; ks++) {
            const int s = ks * 4 + tig;
            float2 p00 = a0p[s], p01 = a1p[s];
            float2 p10 = a2p[s], p11 = a3p[s];
            unsigned ah[2][4], al[2][4];
            hilo_u(p00.x, ah[0][0], al[0][0]); hilo_u(p01.x, ah[0][1], al[0][1]);
            hilo_u(p00.y, ah[0][2], al[0][2]); hilo_u(p01.y, ah[0][3], al[0][3]);
            hilo_u(p10.x, ah[1][0], al[1][0]); hilo_u(p11.x, ah[1][1], al[1][1]);
            hilo_u(p10.y, ah[1][2], al[1][2]); hilo_u(p11.y, ah[1][3], al[1][3]);
            const int ka = ks * 8;
#pragma unroll
            for (int nt = 0; nt < 2; nt++) {
                const int nc = cbase + nt * 8 + gid;
                float2 b0 = *reinterpret_cast<const float2*>(swi + (ka + tig) * SWI2 + 2 * nc);
                float2 b1 = *reinterpret_cast<const float2*>(swi + (ka + tig + 4) * SWI2 + 2 * nc);
                unsigned bh0 = __float_as_uint(b0.x), bl0 = __float_as_uint(b0.y);
                unsigned bh1 = __float_as_uint(b1.x), bl1 = __float_as_uint(b1.y);
#pragma unroll
                for (int mt = 0; mt < 2; mt++) {
                    mma_tf32(acc[mt][nt], ah[mt][0], ah[mt][1], ah[mt][2], ah[mt][3], bh0, bh1);
                    mma_tf32(acc[mt][nt], ah[mt][0], ah[mt][1], ah[mt][2], ah[mt][3], bl0, bl1);
                    mma_tf32(acc[mt][nt], al[mt][0], al[mt][1], al[mt][2], al[mt][3], bh0, bh1);
                }
            }
        }

#pragma unroll
        for (int mt = 0; mt < 2; mt++) {
            const int r0 = rbase + mt * 16 + gid;
#pragma unroll
            for (int nt = 0; nt < 2; nt++) {
                const int cc = cbase + nt * 8 + 2 * tig;
                if (r0 < nv)
                    red_add_v2(out + (size_t)sp[r0].y * COUT + cc,
                               acc[mt][nt].x, acc[mt][nt].y);
                if (r0 + 8 < nv)
                    red_add_v2(out + (size_t)sp[r0 + 8].y * COUT + cc,
                               acc[mt][nt].z, acc[mt][nt].w);
            }
        }
        __syncthreads();
    }
}

// ---------------------------------------------------------------------------
// Inputs: feats f32[N,32], nbr_in_idx i32[K,P], nbr_out_idx i32[K,P],
// nbr_mask f32[K,P], W_in f32[K,32,64], W_out f32[K,64,32]. Output f32[N,32].
// ---------------------------------------------------------------------------
extern "C" void kernel_launch(void* const* d_in, const int* in_sizes, int n_in,
                              void* d_out, int out_size) {
    const float* feats   = (const float*)d_in[0];
    const int*   in_idx  = (const int*)  d_in[1];
    const int*   out_idx = (const int*)  d_in[2];
    const float* mask    = (const float*)d_in[3];
    const float* W_in    = (const float*)d_in[4];
    const float* W_out   = (const float*)d_in[5];
    float*       out     = (float*)      d_out;

    const int N = in_sizes[0] / CIN;
    const int K = in_sizes[4] / (CIN * CMID);
    const int P = in_sizes[3] / K;

    const int smem1 = POOL1F * (int)sizeof(float);   // 37 KB
    const int smem2 = POOL2F * (int)sizeof(float);   // 54 KB
    cudaFuncSetAttribute(fused1_kernel,
        cudaFuncAttributeMaxDynamicSharedMemorySize, smem1);
    cudaFuncSetAttribute(fused2_kernel,
        cudaFuncAttributeMaxDynamicSharedMemorySize, smem2);

    const int n_out4 = N * COUT / 4;
    const int n_h4   = N * CMID / 4;
    const int nmax   = (n_out4 > n_h4) ? n_out4 : n_h4;
    zero_kernel<<<(nmax + 255) / 256, 256>>>((float4*)out, n_out4, n_h4);

    const int wtot = K * CIN * CMID;   // == K*CMID*COUT
    wprep_kernel<<<(wtot + 255) / 256, 256>>>(W_in, W_out, K);

    dim3 gc((P + 255) / 256, K);
    compact_kernel<<<gc, 256>>>(in_idx, out_idx, mask, P);

    const int maxtiles = (P + PT - 1) / PT;
    const int gx = (maxtiles + TILES - 1) / TILES;
    dim3 gf(gx, K);
    fused1_kernel<<<gf, 256, smem1>>>(feats);
    fused2_kernel<<<gf, 256, smem2>>>(out);
}

// round 13
// speedup vs baseline: 1.2061x; 1.1589x over previous
#include <cuda_runtime.h>
#include <cstdint>

// ----------------------------------------------------------------------------
// Fused sparse conv, plain TF32 mma.m16n8k8 (single pass; norm rel-err ~2e-4
// vs 1e-3 gate). W pre-permuted in gmem into fragment order: the two k-rows a
// B-fragment needs are adjacent (one LDS.64). x tf32-converted at staging.
// Block = up to 4 tiles of 128 pairs of one offset k.
// ----------------------------------------------------------------------------

constexpr int CIN   = 32;
constexpr int CMID  = 64;
constexpr int COUT  = 32;
constexpr int MAXK  = 27;
constexpr int MAXP  = 400000;
constexpr int MAXN  = 200192;
constexpr int PT    = 128;       // pairs per tile
constexpr int TILES = 4;         // tiles per block

// x staged as float2 pairs (x[c], x[c+4]); stride in float2 units ≡4 mod 16
// -> conflict-free LDS.64 in both 16-lane phases.
constexpr int SXP1 = 20;
constexpr int SXP2 = 36;
// W fragment rows (ks*4+tig) at stride SWQ float2; 68 ≡ 4 mod 16.
constexpr int SWQ  = 68;
constexpr int WROWS1 = 16;   // 4 ks * 4 tig
constexpr int WROWS2 = 32;   // 8 ks * 4 tig
constexpr int WK1 = WROWS1 * SWQ * 2;   // floats per k (layer1) = 2176
constexpr int WK2 = WROWS2 * SWQ * 2;   // floats per k (layer2) = 4352

constexpr int POOL1F = 2 * PT * SXP1 + WK1;   //  7296 f = 29 KB
constexpr int POOL2F = 2 * PT * SXP2 + WK2;   // 13568 f = 53 KB

__device__ float g_h[(size_t)MAXN * CMID];
__device__ uint2 g_pairs[(size_t)MAXK * MAXP];
__device__ int   g_cnt[MAXK];
__device__ float g_wq1[(size_t)MAXK * WK1];   // W_in  tf32, fragment order
__device__ float g_wq2[(size_t)MAXK * WK2];   // W_out tf32, fragment order

static __device__ __forceinline__ float f2tf_f(float x) {
    unsigned r; asm("cvt.rna.tf32.f32 %0, %1;" : "=r"(r) : "f"(x));
    return __uint_as_float(r);
}
static __device__ __forceinline__ void mma_tf32(
    float4& c, unsigned a0, unsigned a1, unsigned a2, unsigned a3,
    unsigned b0, unsigned b1)
{
    asm volatile(
        "mma.sync.aligned.m16n8k8.row.col.f32.tf32.tf32.f32 "
        "{%0,%1,%2,%3}, {%4,%5,%6,%7}, {%8,%9}, {%0,%1,%2,%3};"
        : "+f"(c.x), "+f"(c.y), "+f"(c.z), "+f"(c.w)
        : "r"(a0), "r"(a1), "r"(a2), "r"(a3), "r"(b0), "r"(b1));
}
static __device__ __forceinline__ void red_add_v2(float* p, float x, float y) {
    asm volatile("red.global.add.v2.f32 [%0], {%1, %2};"
                 :: "l"(p), "f"(x), "f"(y) : "memory");
}

// ---------------------------------------------------------------------------
__global__ void zero_kernel(float4* __restrict__ out, int n_out4, int n_h4) {
    int i = blockIdx.x * blockDim.x + threadIdx.x;
    float4 z = make_float4(0.f, 0.f, 0.f, 0.f);
    if (i < n_out4) out[i] = z;
    if (i < n_h4) reinterpret_cast<float4*>(g_h)[i] = z;
    if (i < MAXK) g_cnt[i] = 0;
}

// ---------------------------------------------------------------------------
// Permute W into fragment order, tf32-rounded.
// B frag (ks,tig,nc) wants rows ka+tig and ka+tig+4 -> float2 at
// [(ks*4+tig)*SWQ + nc], .x = row ka+tig, .y = row ka+tig+4.
// ---------------------------------------------------------------------------
__global__ void wprep_kernel(const float* __restrict__ W_in,
                             const float* __restrict__ W_out, int K) {
    int i = blockIdx.x * blockDim.x + threadIdx.x;
    const int tot = K * CIN * CMID;          // == K*CMID*COUT
    if (i < tot) {   // layer 1: c = r>>6 (0..31), d = r&63
        int k = i / (CIN * CMID), r = i % (CIN * CMID);
        int c = r >> 6, d = r & 63;
        int ks = c >> 3, j = c & 7, tig = j & 3, half = j >> 2;
        g_wq1[(size_t)k * WK1 + ((ks * 4 + tig) * SWQ + d) * 2 + half] =
            f2tf_f(W_in[i]);
    }
    if (i < tot) {   // layer 2: c = r>>5 (0..63), d = r&31
        int k = i / (CMID * COUT), r = i % (CMID * COUT);
        int c = r >> 5, d = r & 31;
        int ks = c >> 3, j = c & 7, tig = j & 3, half = j >> 2;
        g_wq2[(size_t)k * WK2 + ((ks * 4 + tig) * SWQ + d) * 2 + half] =
            f2tf_f(W_out[i]);
    }
}

// ---------------------------------------------------------------------------
__global__ __launch_bounds__(256) void compact_kernel(
    const int* __restrict__ in_idx, const int* __restrict__ out_idx,
    const float* __restrict__ mask, int P)
{
    const int k = blockIdx.y;
    const int p = blockIdx.x * blockDim.x + threadIdx.x;
    bool v = false; int vin = 0, vout = 0;
    if (p < P) {
        size_t o = (size_t)k * P + p;
        v = mask[o] > 0.5f;
        if (v) { vin = in_idx[o]; vout = out_idx[o]; }
    }
    unsigned b = __ballot_sync(0xffffffffu, v);
    int cnt = __popc(b);
    if (cnt == 0) return;
    const int lane = threadIdx.x & 31;
    const int leader = __ffs(b) - 1;
    int base = 0;
    if (lane == leader) base = atomicAdd(&g_cnt[k], cnt);
    base = __shfl_sync(0xffffffffu, base, leader);
    if (v) {
        int off = __popc(b & ((1u << lane) - 1u));
        g_pairs[(size_t)k * MAXP + base + off] =
            make_uint2((unsigned)vin, (unsigned)vout);
    }
}

// ---------------------------------------------------------------------------
// Fused layer 1: g_h[vout][0:64] += feats[vin][0:32] @ W_in[k]
// Warp tile MT=2 (rows 32*(w&3)), NT=4 (cols 32*(w>>2)). K=32 (4 ks).
// ---------------------------------------------------------------------------
__global__ __launch_bounds__(256) void fused1_kernel(
    const float* __restrict__ feats)
{
    const int k    = blockIdx.y;
    const int cnt  = g_cnt[k];
    const int t    = threadIdx.x;
    const int lane = t & 31;
    const int wrp  = t >> 5;

    extern __shared__ float pool[];
    float2* sxp = reinterpret_cast<float2*>(pool);            // [PT][SXP1]
    float2* swq = reinterpret_cast<float2*>(pool + 2 * PT * SXP1);
    __shared__ uint2 sp[PT];

    // Stage W: contiguous float4 copy, once per block.
    {
        const float4* src = reinterpret_cast<const float4*>(g_wq1 + (size_t)k * WK1);
        float4* dst = reinterpret_cast<float4*>(swq);
        for (int i = t; i < WK1 / 4; i += 256) dst[i] = src[i];
    }

    const int gid = lane >> 2, tig = lane & 3;
    const int rbase = 32 * (wrp & 3);
    const int cbase = 32 * (wrp >> 2);
    const float2* a0p = sxp + (rbase + gid) * SXP1;
    const float2* a1p = a0p + 8 * SXP1;
    const float2* a2p = a0p + 16 * SXP1;
    const float2* a3p = a0p + 24 * SXP1;
    const float2* wrow = swq + tig * SWQ;      // + ks*4*SWQ per step

    for (int tile = blockIdx.x; tile * PT < cnt; tile += gridDim.x) {
        const int base = tile * PT;
        const int nv   = min(PT, cnt - base);

        // ---- gather: pair recs + x rows, tf32-rounded, paired layout ----
        {
            const int r = t >> 1, half = t & 1;
            uint2 pr = (r < nv) ? g_pairs[(size_t)k * MAXP + base + r]
                                : make_uint2(0u, 0u);
            if (half == 0) sp[r] = pr;
            const float4* src = reinterpret_cast<const float4*>(feats + (size_t)pr.x * CIN);
            float4* drow = reinterpret_cast<float4*>(sxp + r * SXP1);
#pragma unroll
            for (int b = 0; b < 2; b++) {
                const int ab = 2 * half + b;
                float4 va = src[2 * ab], vb = src[2 * ab + 1];
                drow[ab * 2]     = make_float4(f2tf_f(va.x), f2tf_f(vb.x),
                                               f2tf_f(va.y), f2tf_f(vb.y));
                drow[ab * 2 + 1] = make_float4(f2tf_f(va.z), f2tf_f(vb.z),
                                               f2tf_f(va.w), f2tf_f(vb.w));
            }
        }
        __syncthreads();

        float4 acc[2][4];
#pragma unroll
        for (int mt = 0; mt < 2; mt++)
#pragma unroll
            for (int nt = 0; nt < 4; nt++) acc[mt][nt] = make_float4(0.f, 0.f, 0.f, 0.f);

#pragma unroll
        for (int ks = 0; ks < 4; ks++) {
            const int s = ks * 4 + tig;
            float2 p00 = a0p[s], p01 = a1p[s];
            float2 p10 = a2p[s], p11 = a3p[s];
            unsigned a00 = __float_as_uint(p00.x), a01 = __float_as_uint(p01.x);
            unsigned a02 = __float_as_uint(p00.y), a03 = __float_as_uint(p01.y);
            unsigned a10 = __float_as_uint(p10.x), a11 = __float_as_uint(p11.x);
            unsigned a12 = __float_as_uint(p10.y), a13 = __float_as_uint(p11.y);
            const float2* wk = wrow + ks * 4 * SWQ;
#pragma unroll
            for (int nt = 0; nt < 4; nt++) {
                float2 b = wk[cbase + nt * 8 + gid];
                unsigned b0 = __float_as_uint(b.x), b1 = __float_as_uint(b.y);
                mma_tf32(acc[0][nt], a00, a01, a02, a03, b0, b1);
                mma_tf32(acc[1][nt], a10, a11, a12, a13, b0, b1);
            }
        }

        // ---- scatter straight from accumulators ----
#pragma unroll
        for (int mt = 0; mt < 2; mt++) {
            const int r0 = rbase + mt * 16 + gid;
#pragma unroll
            for (int nt = 0; nt < 4; nt++) {
                const int cc = cbase + nt * 8 + 2 * tig;
                if (r0 < nv)
                    red_add_v2(g_h + (size_t)sp[r0].y * CMID + cc,
                               acc[mt][nt].x, acc[mt][nt].y);
                if (r0 + 8 < nv)
                    red_add_v2(g_h + (size_t)sp[r0 + 8].y * CMID + cc,
                               acc[mt][nt].z, acc[mt][nt].w);
            }
        }
        __syncthreads();
    }
}

// ---------------------------------------------------------------------------
// Fused layer 2: out[vout][0:32] += relu(g_h[vin][0:64]) @ W_out[k]
// Warp tile MT=2 (rows 32*(w&3)), NT=2 (cols 16*(w>>2)). K=64 (8 ks).
// ---------------------------------------------------------------------------
__global__ __launch_bounds__(256) void fused2_kernel(float* __restrict__ out)
{
    const int k    = blockIdx.y;
    const int cnt  = g_cnt[k];
    const int t    = threadIdx.x;
    const int lane = t & 31;
    const int wrp  = t >> 5;

    extern __shared__ float pool[];
    float2* sxp = reinterpret_cast<float2*>(pool);            // [PT][SXP2]
    float2* swq = reinterpret_cast<float2*>(pool + 2 * PT * SXP2);
    __shared__ uint2 sp[PT];

    {
        const float4* src = reinterpret_cast<const float4*>(g_wq2 + (size_t)k * WK2);
        float4* dst = reinterpret_cast<float4*>(swq);
        for (int i = t; i < WK2 / 4; i += 256) dst[i] = src[i];
    }

    const int gid = lane >> 2, tig = lane & 3;
    const int rbase = 32 * (wrp & 3);
    const int cbase = 16 * (wrp >> 2);
    const float2* a0p = sxp + (rbase + gid) * SXP2;
    const float2* a1p = a0p + 8 * SXP2;
    const float2* a2p = a0p + 16 * SXP2;
    const float2* a3p = a0p + 24 * SXP2;
    const float2* wrow = swq + tig * SWQ;

    for (int tile = blockIdx.x; tile * PT < cnt; tile += gridDim.x) {
        const int base = tile * PT;
        const int nv   = min(PT, cnt - base);

        // ---- gather: pair recs + relu(h) rows, tf32, paired layout ----
        {
            const int r = t >> 1, half = t & 1;
            uint2 pr = (r < nv) ? g_pairs[(size_t)k * MAXP + base + r]
                                : make_uint2(0u, 0u);
            if (half == 0) sp[r] = pr;
            const float4* src = reinterpret_cast<const float4*>(g_h + (size_t)pr.x * CMID);
            float4* drow = reinterpret_cast<float4*>(sxp + r * SXP2);
#pragma unroll
            for (int b = 0; b < 4; b++) {
                const int ab = 4 * half + b;
                float4 va = src[2 * ab], vb = src[2 * ab + 1];
                drow[ab * 2]     = make_float4(f2tf_f(fmaxf(va.x, 0.f)), f2tf_f(fmaxf(vb.x, 0.f)),
                                               f2tf_f(fmaxf(va.y, 0.f)), f2tf_f(fmaxf(vb.y, 0.f)));
                drow[ab * 2 + 1] = make_float4(f2tf_f(fmaxf(va.z, 0.f)), f2tf_f(fmaxf(vb.z, 0.f)),
                                               f2tf_f(fmaxf(va.w, 0.f)), f2tf_f(fmaxf(vb.w, 0.f)));
            }
        }
        __syncthreads();

        float4 acc[2][2];
#pragma unroll
        for (int mt = 0; mt < 2; mt++)
#pragma unroll
            for (int nt = 0; nt < 2; nt++) acc[mt][nt] = make_float4(0.f, 0.f, 0.f, 0.f);

#pragma unroll
        for (int ks = 0; ks < 8; ks++) {
            const int s = ks * 4 + tig;
            float2 p00 = a0p[s], p01 = a1p[s];
            float2 p10 = a2p[s], p11 = a3p[s];
            unsigned a00 = __float_as_uint(p00.x), a01 = __float_as_uint(p01.x);
            unsigned a02 = __float_as_uint(p00.y), a03 = __float_as_uint(p01.y);
            unsigned a10 = __float_as_uint(p10.x), a11 = __float_as_uint(p11.x);
            unsigned a12 = __float_as_uint(p10.y), a13 = __float_as_uint(p11.y);
            const float2* wk = wrow + ks * 4 * SWQ;
#pragma unroll
            for (int nt = 0; nt < 2; nt++) {
                float2 b = wk[cbase + nt * 8 + gid];
                unsigned b0 = __float_as_uint(b.x), b1 = __float_as_uint(b.y);
                mma_tf32(acc[0][nt], a00, a01, a02, a03, b0, b1);
                mma_tf32(acc[1][nt], a10, a11, a12, a13, b0, b1);
            }
        }

#pragma unroll
        for (int mt = 0; mt < 2; mt++) {
            const int r0 = rbase + mt * 16 + gid;
#pragma unroll
            for (int nt = 0; nt < 2; nt++) {
                const int cc = cbase + nt * 8 + 2 * tig;
                if (r0 < nv)
                    red_add_v2(out + (size_t)sp[r0].y * COUT + cc,
                               acc[mt][nt].x, acc[mt][nt].y);
                if (r0 + 8 < nv)
                    red_add_v2(out + (size_t)sp[r0 + 8].y * COUT + cc,
                               acc[mt][nt].z, acc[mt][nt].w);
            }
        }
        __syncthreads();
    }
}

// ---------------------------------------------------------------------------
// Inputs: feats f32[N,32], nbr_in_idx i32[K,P], nbr_out_idx i32[K,P],
// nbr_mask f32[K,P], W_in f32[K,32,64], W_out f32[K,64,32]. Output f32[N,32].
// ---------------------------------------------------------------------------
extern "C" void kernel_launch(void* const* d_in, const int* in_sizes, int n_in,
                              void* d_out, int out_size) {
    const float* feats   = (const float*)d_in[0];
    const int*   in_idx  = (const int*)  d_in[1];
    const int*   out_idx = (const int*)  d_in[2];
    const float* mask    = (const float*)d_in[3];
    const float* W_in    = (const float*)d_in[4];
    const float* W_out   = (const float*)d_in[5];
    float*       out     = (float*)      d_out;

    const int N = in_sizes[0] / CIN;
    const int K = in_sizes[4] / (CIN * CMID);
    const int P = in_sizes[3] / K;

    const int smem1 = POOL1F * (int)sizeof(float);   // ~29 KB
    const int smem2 = POOL2F * (int)sizeof(float);   // ~53 KB
    cudaFuncSetAttribute(fused1_kernel,
        cudaFuncAttributeMaxDynamicSharedMemorySize, smem1);
    cudaFuncSetAttribute(fused2_kernel,
        cudaFuncAttributeMaxDynamicSharedMemorySize, smem2);

    const int n_out4 = N * COUT / 4;
    const int n_h4   = N * CMID / 4;
    const int nmax   = (n_out4 > n_h4) ? n_out4 : n_h4;
    zero_kernel<<<(nmax + 255) / 256, 256>>>((float4*)out, n_out4, n_h4);

    const int wtot = K * CIN * CMID;
    wprep_kernel<<<(wtot + 255) / 256, 256>>>(W_in, W_out, K);

    dim3 gc((P + 255) / 256, K);
    compact_kernel<<<gc, 256>>>(in_idx, out_idx, mask, P);

    const int maxtiles = (P + PT - 1) / PT;
    const int gx = (maxtiles + TILES - 1) / TILES;
    dim3 gf(gx, K);
    fused1_kernel<<<gf, 256, smem1>>>(feats);
    fused2_kernel<<<gf, 256, smem2>>>(out);
}

// round 14
// speedup vs baseline: 1.3355x; 1.1073x over previous
#include <cuda_runtime.h>
#include <cstdint>

// ----------------------------------------------------------------------------
// Fused sparse conv, plain TF32 mma.m16n8k8. W pre-permuted in gmem:
//  - k-rows in fragment order (one LDS.64 per B fragment)
//  - output channels permuted within 16-groups so each thread's accumulators
//    from two adjacent n-tiles cover 4 CONSECUTIVE channels -> red.v4 scatter
//    straight from registers (half the red instructions of red.v2).
// Block = up to 4 tiles of 128 pairs of one offset k.
// ----------------------------------------------------------------------------

constexpr int CIN   = 32;
constexpr int CMID  = 64;
constexpr int COUT  = 32;
constexpr int MAXK  = 27;
constexpr int MAXP  = 400000;
constexpr int MAXN  = 200192;
constexpr int PT    = 128;       // pairs per tile
constexpr int TILES = 4;         // tiles per block

// x staged as float2 pairs (x[c], x[c+4]); stride ≡4 mod 16 float2 -> LDS.64 ok.
constexpr int SXP1 = 20;
constexpr int SXP2 = 36;
// W fragment rows (ks*4+tig) at stride SWQ float2; 68 ≡ 4 mod 16.
constexpr int SWQ  = 68;
constexpr int WK1  = 16 * SWQ * 2;   // floats per k (layer1) = 2176
constexpr int WK2  = 32 * SWQ * 2;   // floats per k (layer2) = 4352

constexpr int POOL1F = 2 * PT * SXP1 + WK1;   //  7296 f = 29 KB
constexpr int POOL2F = 2 * PT * SXP2 + WK2;   // 13568 f = 53 KB

__device__ float g_h[(size_t)MAXN * CMID];
__device__ uint2 g_pairs[(size_t)MAXK * MAXP];
__device__ int   g_cnt[MAXK];
__device__ float g_wq1[(size_t)MAXK * WK1];
__device__ float g_wq2[(size_t)MAXK * WK2];

static __device__ __forceinline__ float f2tf_f(float x) {
    unsigned r; asm("cvt.rna.tf32.f32 %0, %1;" : "=r"(r) : "f"(x));
    return __uint_as_float(r);
}
static __device__ __forceinline__ void mma_tf32(
    float4& c, unsigned a0, unsigned a1, unsigned a2, unsigned a3,
    unsigned b0, unsigned b1)
{
    asm volatile(
        "mma.sync.aligned.m16n8k8.row.col.f32.tf32.tf32.f32 "
        "{%0,%1,%2,%3}, {%4,%5,%6,%7}, {%8,%9}, {%0,%1,%2,%3};"
        : "+f"(c.x), "+f"(c.y), "+f"(c.z), "+f"(c.w)
        : "r"(a0), "r"(a1), "r"(a2), "r"(a3), "r"(b0), "r"(b1));
}
static __device__ __forceinline__ void red_add_v4(float* p, float4 v) {
    asm volatile("red.global.add.v4.f32 [%0], {%1, %2, %3, %4};"
                 :: "l"(p), "f"(v.x), "f"(v.y), "f"(v.z), "f"(v.w) : "memory");
}

// ---------------------------------------------------------------------------
__global__ void zero_kernel(float4* __restrict__ out, int n_out4, int n_h4) {
    int i = blockIdx.x * blockDim.x + threadIdx.x;
    float4 z = make_float4(0.f, 0.f, 0.f, 0.f);
    if (i < n_out4) out[i] = z;
    if (i < n_h4) reinterpret_cast<float4*>(g_h)[i] = z;
    if (i < MAXK) g_cnt[i] = 0;
}

// ---------------------------------------------------------------------------
// Permute W: k-rows into fragment order + output-channel perm within
// 16-groups. Channel dc (in 32-/16-block): tg=(dc mod 16)>>2, rem=dc&3,
// sub=rem>>1, b=rem&1 -> MMA tile pair-member `sub`, col j=2*tg+b.
// Then thread (gid,tig) holds channels 4*tig..4*tig+3 across the tile pair.
// ---------------------------------------------------------------------------
__global__ void wprep_kernel(const float* __restrict__ W_in,
                             const float* __restrict__ W_out, int K) {
    int i = blockIdx.x * blockDim.x + threadIdx.x;
    const int tot = K * CIN * CMID;          // == K*CMID*COUT
    if (i < tot) {   // layer 1: c in [0,32) k-dim, d in [0,64) channel
        int k = i / (CIN * CMID), r = i % (CIN * CMID);
        int c = r >> 6, d = r & 63;
        int ks = c >> 3, j = c & 7, tig = j & 3, half = j >> 2;
        int dc = d & 31, dhi = d & ~31;
        int tg = (dc & 15) >> 2, rem = dc & 3, sub = rem >> 1, b = rem & 1;
        int slot = (2 * ((dc >> 4) & 1) + sub) * 8 + 2 * tg + b;
        g_wq1[(size_t)k * WK1 + ((ks * 4 + tig) * SWQ + (dhi | slot)) * 2 + half] =
            f2tf_f(W_in[i]);
    }
    if (i < tot) {   // layer 2: c in [0,64), d in [0,32)
        int k = i / (CMID * COUT), r = i % (CMID * COUT);
        int c = r >> 5, d = r & 31;
        int ks = c >> 3, j = c & 7, tig = j & 3, half = j >> 2;
        int dc = d & 15, dhi = d & ~15;
        int tg = dc >> 2, rem = dc & 3, sub = rem >> 1, b = rem & 1;
        int slot = sub * 8 + 2 * tg + b;
        g_wq2[(size_t)k * WK2 + ((ks * 4 + tig) * SWQ + (dhi | slot)) * 2 + half] =
            f2tf_f(W_out[i]);
    }
}

// ---------------------------------------------------------------------------
__global__ __launch_bounds__(256) void compact_kernel(
    const int* __restrict__ in_idx, const int* __restrict__ out_idx,
    const float* __restrict__ mask, int P)
{
    const int k = blockIdx.y;
    const int p = blockIdx.x * blockDim.x + threadIdx.x;
    bool v = false; int vin = 0, vout = 0;
    if (p < P) {
        size_t o = (size_t)k * P + p;
        v = mask[o] > 0.5f;
        if (v) { vin = in_idx[o]; vout = out_idx[o]; }
    }
    unsigned b = __ballot_sync(0xffffffffu, v);
    int cnt = __popc(b);
    if (cnt == 0) return;
    const int lane = threadIdx.x & 31;
    const int leader = __ffs(b) - 1;
    int base = 0;
    if (lane == leader) base = atomicAdd(&g_cnt[k], cnt);
    base = __shfl_sync(0xffffffffu, base, leader);
    if (v) {
        int off = __popc(b & ((1u << lane) - 1u));
        g_pairs[(size_t)k * MAXP + base + off] =
            make_uint2((unsigned)vin, (unsigned)vout);
    }
}

// ---------------------------------------------------------------------------
// Fused layer 1: g_h[vout][0:64] += feats[vin][0:32] @ W_in[k]
// Warp tile MT=2 (rows 32*(w&3)), NT=4 (cols 32*(w>>2)). K=32 (4 ks).
// ---------------------------------------------------------------------------
__global__ __launch_bounds__(256) void fused1_kernel(
    const float* __restrict__ feats)
{
    const int k    = blockIdx.y;
    const int cnt  = g_cnt[k];
    const int t    = threadIdx.x;
    const int lane = t & 31;
    const int wrp  = t >> 5;

    extern __shared__ float pool[];
    float2* sxp = reinterpret_cast<float2*>(pool);            // [PT][SXP1]
    float2* swq = reinterpret_cast<float2*>(pool + 2 * PT * SXP1);
    __shared__ uint2 sp[PT];

    {   // W stage: contiguous float4 copy, once per block
        const float4* src = reinterpret_cast<const float4*>(g_wq1 + (size_t)k * WK1);
        float4* dst = reinterpret_cast<float4*>(swq);
        for (int i = t; i < WK1 / 4; i += 256) dst[i] = src[i];
    }

    const int gid = lane >> 2, tig = lane & 3;
    const int rbase = 32 * (wrp & 3);
    const int cbase = 32 * (wrp >> 2);
    const float2* a0p = sxp + (rbase + gid) * SXP1;
    const float2* a1p = a0p + 8 * SXP1;
    const float2* a2p = a0p + 16 * SXP1;
    const float2* a3p = a0p + 24 * SXP1;
    const float2* wrow = swq + tig * SWQ;

    for (int tile = blockIdx.x; tile * PT < cnt; tile += gridDim.x) {
        const int base = tile * PT;
        const int nv   = min(PT, cnt - base);

        {   // gather: pair recs + x rows, tf32-rounded, paired layout
            const int r = t >> 1, half = t & 1;
            uint2 pr = (r < nv) ? g_pairs[(size_t)k * MAXP + base + r]
                                : make_uint2(0u, 0u);
            if (half == 0) sp[r] = pr;
            const float4* src = reinterpret_cast<const float4*>(feats + (size_t)pr.x * CIN);
            float4* drow = reinterpret_cast<float4*>(sxp + r * SXP1);
#pragma unroll
            for (int b = 0; b < 2; b++) {
                const int ab = 2 * half + b;
                float4 va = src[2 * ab], vb = src[2 * ab + 1];
                drow[ab * 2]     = make_float4(f2tf_f(va.x), f2tf_f(vb.x),
                                               f2tf_f(va.y), f2tf_f(vb.y));
                drow[ab * 2 + 1] = make_float4(f2tf_f(va.z), f2tf_f(vb.z),
                                               f2tf_f(va.w), f2tf_f(vb.w));
            }
        }
        __syncthreads();

        float4 acc[2][4];
#pragma unroll
        for (int mt = 0; mt < 2; mt++)
#pragma unroll
            for (int nt = 0; nt < 4; nt++) acc[mt][nt] = make_float4(0.f, 0.f, 0.f, 0.f);

#pragma unroll
        for (int ks = 0; ks < 4; ks++) {
            const int s = ks * 4 + tig;
            float2 p00 = a0p[s], p01 = a1p[s];
            float2 p10 = a2p[s], p11 = a3p[s];
            unsigned a00 = __float_as_uint(p00.x), a01 = __float_as_uint(p01.x);
            unsigned a02 = __float_as_uint(p00.y), a03 = __float_as_uint(p01.y);
            unsigned a10 = __float_as_uint(p10.x), a11 = __float_as_uint(p11.x);
            unsigned a12 = __float_as_uint(p10.y), a13 = __float_as_uint(p11.y);
            const float2* wk = wrow + ks * 4 * SWQ;
#pragma unroll
            for (int nt = 0; nt < 4; nt++) {
                float2 b = wk[cbase + nt * 8 + gid];
                unsigned b0 = __float_as_uint(b.x), b1 = __float_as_uint(b.y);
                mma_tf32(acc[0][nt], a00, a01, a02, a03, b0, b1);
                mma_tf32(acc[1][nt], a10, a11, a12, a13, b0, b1);
            }
        }

        // scatter: permuted channels -> red.v4 from accumulator pairs
#pragma unroll
        for (int mt = 0; mt < 2; mt++) {
            const int r0 = rbase + mt * 16 + gid;
#pragma unroll
            for (int q = 0; q < 2; q++) {
                const int cc = cbase + 16 * q + 4 * tig;
                if (r0 < nv)
                    red_add_v4(g_h + (size_t)sp[r0].y * CMID + cc,
                               make_float4(acc[mt][2 * q].x,     acc[mt][2 * q].y,
                                           acc[mt][2 * q + 1].x, acc[mt][2 * q + 1].y));
                if (r0 + 8 < nv)
                    red_add_v4(g_h + (size_t)sp[r0 + 8].y * CMID + cc,
                               make_float4(acc[mt][2 * q].z,     acc[mt][2 * q].w,
                                           acc[mt][2 * q + 1].z, acc[mt][2 * q + 1].w));
            }
        }
        __syncthreads();
    }
}

// ---------------------------------------------------------------------------
// Fused layer 2: out[vout][0:32] += relu(g_h[vin][0:64]) @ W_out[k]
// Warp tile MT=2 (rows 32*(w&3)), NT=2 (cols 16*(w>>2)). K=64 (8 ks).
// ---------------------------------------------------------------------------
__global__ __launch_bounds__(256) void fused2_kernel(float* __restrict__ out)
{
    const int k    = blockIdx.y;
    const int cnt  = g_cnt[k];
    const int t    = threadIdx.x;
    const int lane = t & 31;
    const int wrp  = t >> 5;

    extern __shared__ float pool[];
    float2* sxp = reinterpret_cast<float2*>(pool);            // [PT][SXP2]
    float2* swq = reinterpret_cast<float2*>(pool + 2 * PT * SXP2);
    __shared__ uint2 sp[PT];

    {
        const float4* src = reinterpret_cast<const float4*>(g_wq2 + (size_t)k * WK2);
        float4* dst = reinterpret_cast<float4*>(swq);
        for (int i = t; i < WK2 / 4; i += 256) dst[i] = src[i];
    }

    const int gid = lane >> 2, tig = lane & 3;
    const int rbase = 32 * (wrp & 3);
    const int cbase = 16 * (wrp >> 2);
    const float2* a0p = sxp + (rbase + gid) * SXP2;
    const float2* a1p = a0p + 8 * SXP2;
    const float2* a2p = a0p + 16 * SXP2;
    const float2* a3p = a0p + 24 * SXP2;
    const float2* wrow = swq + tig * SWQ;

    for (int tile = blockIdx.x; tile * PT < cnt; tile += gridDim.x) {
        const int base = tile * PT;
        const int nv   = min(PT, cnt - base);

        {   // gather: pair recs + relu(h) rows, tf32, paired layout
            const int r = t >> 1, half = t & 1;
            uint2 pr = (r < nv) ? g_pairs[(size_t)k * MAXP + base + r]
                                : make_uint2(0u, 0u);
            if (half == 0) sp[r] = pr;
            const float4* src = reinterpret_cast<const float4*>(g_h + (size_t)pr.x * CMID);
            float4* drow = reinterpret_cast<float4*>(sxp + r * SXP2);
#pragma unroll
            for (int b = 0; b < 4; b++) {
                const int ab = 4 * half + b;
                float4 va = src[2 * ab], vb = src[2 * ab + 1];
                drow[ab * 2]     = make_float4(f2tf_f(fmaxf(va.x, 0.f)), f2tf_f(fmaxf(vb.x, 0.f)),
                                               f2tf_f(fmaxf(va.y, 0.f)), f2tf_f(fmaxf(vb.y, 0.f)));
                drow[ab * 2 + 1] = make_float4(f2tf_f(fmaxf(va.z, 0.f)), f2tf_f(fmaxf(vb.z, 0.f)),
                                               f2tf_f(fmaxf(va.w, 0.f)), f2tf_f(fmaxf(vb.w, 0.f)));
            }
        }
        __syncthreads();

        float4 acc[2][2];
#pragma unroll
        for (int mt = 0; mt < 2; mt++)
#pragma unroll
            for (int nt = 0; nt < 2; nt++) acc[mt][nt] = make_float4(0.f, 0.f, 0.f, 0.f);

#pragma unroll
        for (int ks = 0; ks < 8; ks++) {
            const int s = ks * 4 + tig;
            float2 p00 = a0p[s], p01 = a1p[s];
            float2 p10 = a2p[s], p11 = a3p[s];
            unsigned a00 = __float_as_uint(p00.x), a01 = __float_as_uint(p01.x);
            unsigned a02 = __float_as_uint(p00.y), a03 = __float_as_uint(p01.y);
            unsigned a10 = __float_as_uint(p10.x), a11 = __float_as_uint(p11.x);
            unsigned a12 = __float_as_uint(p10.y), a13 = __float_as_uint(p11.y);
            const float2* wk = wrow + ks * 4 * SWQ;
#pragma unroll
            for (int nt = 0; nt < 2; nt++) {
                float2 b = wk[cbase + nt * 8 + gid];
                unsigned b0 = __float_as_uint(b.x), b1 = __float_as_uint(b.y);
                mma_tf32(acc[0][nt], a00, a01, a02, a03, b0, b1);
                mma_tf32(acc[1][nt], a10, a11, a12, a13, b0, b1);
            }
        }

        // scatter: permuted channels -> one red.v4 per row per mt
#pragma unroll
        for (int mt = 0; mt < 2; mt++) {
            const int r0 = rbase + mt * 16 + gid;
            const int cc = cbase + 4 * tig;
            if (r0 < nv)
                red_add_v4(out + (size_t)sp[r0].y * COUT + cc,
                           make_float4(acc[mt][0].x, acc[mt][0].y,
                                       acc[mt][1].x, acc[mt][1].y));
            if (r0 + 8 < nv)
                red_add_v4(out + (size_t)sp[r0 + 8].y * COUT + cc,
                           make_float4(acc[mt][0].z, acc[mt][0].w,
                                       acc[mt][1].z, acc[mt][1].w));
        }
        __syncthreads();
    }
}

// ---------------------------------------------------------------------------
// Inputs: feats f32[N,32], nbr_in_idx i32[K,P], nbr_out_idx i32[K,P],
// nbr_mask f32[K,P], W_in f32[K,32,64], W_out f32[K,64,32]. Output f32[N,32].
// ---------------------------------------------------------------------------
extern "C" void kernel_launch(void* const* d_in, const int* in_sizes, int n_in,
                              void* d_out, int out_size) {
    const float* feats   = (const float*)d_in[0];
    const int*   in_idx  = (const int*)  d_in[1];
    const int*   out_idx = (const int*)  d_in[2];
    const float* mask    = (const float*)d_in[3];
    const float* W_in    = (const float*)d_in[4];
    const float* W_out   = (const float*)d_in[5];
    float*       out     = (float*)      d_out;

    const int N = in_sizes[0] / CIN;
    const int K = in_sizes[4] / (CIN * CMID);
    const int P = in_sizes[3] / K;

    const int smem1 = POOL1F * (int)sizeof(float);
    const int smem2 = POOL2F * (int)sizeof(float);
    cudaFuncSetAttribute(fused1_kernel,
        cudaFuncAttributeMaxDynamicSharedMemorySize, smem1);
    cudaFuncSetAttribute(fused2_kernel,
        cudaFuncAttributeMaxDynamicSharedMemorySize, smem2);

    const int n_out4 = N * COUT / 4;
    const int n_h4   = N * CMID / 4;
    const int nmax   = (n_out4 > n_h4) ? n_out4 : n_h4;
    zero_kernel<<<(nmax + 255) / 256, 256>>>((float4*)out, n_out4, n_h4);

    const int wtot = K * CIN * CMID;
    wprep_kernel<<<(wtot + 255) / 256, 256>>>(W_in, W_out, K);

    dim3 gc((P + 255) / 256, K);
    compact_kernel<<<gc, 256>>>(in_idx, out_idx, mask, P);

    const int maxtiles = (P + PT - 1) / PT;
    const int gx = (maxtiles + TILES - 1) / TILES;
    dim3 gf(gx, K);
    fused1_kernel<<<gf, 256, smem1>>>(feats);
    fused2_kernel<<<gf, 256, smem2>>>(out);
}

// round 15
// speedup vs baseline: 1.6350x; 1.2242x over previous
#include <cuda_runtime.h>
#include <cstdint>

// ----------------------------------------------------------------------------
// Fused sparse conv, plain TF32 m16n8k8, cp.async double-buffered pipeline.
// W pre-permuted (fragment-ordered k-rows + channel perm -> red.v4 scatter).
// x staged RAW via cp.async; tf32 cvt (+ReLU L2) at fragment-load time.
// One commit-group + one __syncthreads per tile; next gather under current MMA.
// ----------------------------------------------------------------------------

constexpr int CIN   = 32;
constexpr int CMID  = 64;
constexpr int COUT  = 32;
constexpr int MAXK  = 27;
constexpr int MAXP  = 400000;
constexpr int MAXN  = 200192;
constexpr int PT1   = 128;      // pairs per tile, layer 1
constexpr int PT2   = 64;       // pairs per tile, layer 2

constexpr int SX1R = 36;        // raw x row stride (floats); 36%32=4 -> bank-ok, 144B=16B-mult
constexpr int SX2R = 68;        // 68%32=4, 272B=16B-mult
constexpr int SWQ  = 68;        // W fragment-row stride (float2)
constexpr int WK1  = 16 * SWQ * 2;   // 2176 floats
constexpr int WK2  = 32 * SWQ * 2;   // 4352 floats

constexpr int POOL1F = 2 * PT1 * SX1R + WK1;   // 11392 f = 45.6 KB
constexpr int POOL2F = 2 * PT2 * SX2R + WK2;   // 13056 f = 52.2 KB

__device__ float g_h[(size_t)MAXN * CMID];
__device__ uint2 g_pairs[(size_t)MAXK * MAXP];
__device__ int   g_cnt[MAXK];
__device__ float g_wq1[(size_t)MAXK * WK1];
__device__ float g_wq2[(size_t)MAXK * WK2];

static __device__ __forceinline__ unsigned f2tf(float x) {
    unsigned r; asm("cvt.rna.tf32.f32 %0, %1;" : "=r"(r) : "f"(x)); return r;
}
static __device__ __forceinline__ float f2tf_f(float x) {
    return __uint_as_float(f2tf(x));
}
static __device__ __forceinline__ void mma_tf32(
    float4& c, unsigned a0, unsigned a1, unsigned a2, unsigned a3,
    unsigned b0, unsigned b1)
{
    asm volatile(
        "mma.sync.aligned.m16n8k8.row.col.f32.tf32.tf32.f32 "
        "{%0,%1,%2,%3}, {%4,%5,%6,%7}, {%8,%9}, {%0,%1,%2,%3};"
        : "+f"(c.x), "+f"(c.y), "+f"(c.z), "+f"(c.w)
        : "r"(a0), "r"(a1), "r"(a2), "r"(a3), "r"(b0), "r"(b1));
}
static __device__ __forceinline__ void red_add_v4(float* p, float4 v) {
    asm volatile("red.global.add.v4.f32 [%0], {%1, %2, %3, %4};"
                 :: "l"(p), "f"(v.x), "f"(v.y), "f"(v.z), "f"(v.w) : "memory");
}
static __device__ __forceinline__ void cp_async16(float* smem, const float* g) {
    unsigned s = (unsigned)__cvta_generic_to_shared(smem);
    asm volatile("cp.async.ca.shared.global [%0], [%1], 16;" :: "r"(s), "l"(g));
}
#define CP_COMMIT() asm volatile("cp.async.commit_group;" ::: "memory")
#define CP_WAIT0()  asm volatile("cp.async.wait_group 0;"  ::: "memory")

// ---------------------------------------------------------------------------
__global__ void zero_kernel(float4* __restrict__ out, int n_out4, int n_h4) {
    int i = blockIdx.x * blockDim.x + threadIdx.x;
    float4 z = make_float4(0.f, 0.f, 0.f, 0.f);
    if (i < n_out4) out[i] = z;
    if (i < n_h4) reinterpret_cast<float4*>(g_h)[i] = z;
    if (i < MAXK) g_cnt[i] = 0;
}

// ---------------------------------------------------------------------------
// W permute (identical math to R14): fragment-ordered k-rows + channel perm.
// ---------------------------------------------------------------------------
__global__ void wprep_kernel(const float* __restrict__ W_in,
                             const float* __restrict__ W_out, int K) {
    int i = blockIdx.x * blockDim.x + threadIdx.x;
    const int tot = K * CIN * CMID;
    if (i < tot) {   // layer 1
        int k = i / (CIN * CMID), r = i % (CIN * CMID);
        int c = r >> 6, d = r & 63;
        int ks = c >> 3, j = c & 7, tig = j & 3, half = j >> 2;
        int dc = d & 31, dhi = d & ~31;
        int tg = (dc & 15) >> 2, rem = dc & 3, sub = rem >> 1, b = rem & 1;
        int slot = (2 * ((dc >> 4) & 1) + sub) * 8 + 2 * tg + b;
        g_wq1[(size_t)k * WK1 + ((ks * 4 + tig) * SWQ + (dhi | slot)) * 2 + half] =
            f2tf_f(W_in[i]);
    }
    if (i < tot) {   // layer 2
        int k = i / (CMID * COUT), r = i % (CMID * COUT);
        int c = r >> 5, d = r & 31;
        int ks = c >> 3, j = c & 7, tig = j & 3, half = j >> 2;
        int dc = d & 15, dhi = d & ~15;
        int tg = dc >> 2, rem = dc & 3, sub = rem >> 1, b = rem & 1;
        int slot = sub * 8 + 2 * tg + b;
        g_wq2[(size_t)k * WK2 + ((ks * 4 + tig) * SWQ + (dhi | slot)) * 2 + half] =
            f2tf_f(W_out[i]);
    }
}

// ---------------------------------------------------------------------------
__global__ __launch_bounds__(256) void compact_kernel(
    const int* __restrict__ in_idx, const int* __restrict__ out_idx,
    const float* __restrict__ mask, int P)
{
    const int k = blockIdx.y;
    const int p = blockIdx.x * blockDim.x + threadIdx.x;
    bool v = false; int vin = 0, vout = 0;
    if (p < P) {
        size_t o = (size_t)k * P + p;
        v = mask[o] > 0.5f;
        if (v) { vin = in_idx[o]; vout = out_idx[o]; }
    }
    unsigned b = __ballot_sync(0xffffffffu, v);
    int cnt = __popc(b);
    if (cnt == 0) return;
    const int lane = threadIdx.x & 31;
    const int leader = __ffs(b) - 1;
    int base = 0;
    if (lane == leader) base = atomicAdd(&g_cnt[k], cnt);
    base = __shfl_sync(0xffffffffu, base, leader);
    if (v) {
        int off = __popc(b & ((1u << lane) - 1u));
        g_pairs[(size_t)k * MAXP + base + off] =
            make_uint2((unsigned)vin, (unsigned)vout);
    }
}

// ---------------------------------------------------------------------------
// Fused layer 1 (pipelined): g_h[vout][0:64] += feats[vin][0:32] @ W_in[k]
// Warp tile MT=2 (rows 32*(w&3)), NT=4 (cols 32*(w>>2)). K=32.
// ---------------------------------------------------------------------------
__global__ __launch_bounds__(256) void fused1_kernel(
    const float* __restrict__ feats)
{
    const int k   = blockIdx.y;
    const int cnt = g_cnt[k];
    if (blockIdx.x * PT1 >= cnt) return;
    const int t    = threadIdx.x;
    const int lane = t & 31;
    const int wrp  = t >> 5;

    extern __shared__ float pool[];
    float*  xb  = pool;                                   // [2][PT1][SX1R]
    float2* swq = reinterpret_cast<float2*>(pool + 2 * PT1 * SX1R);
    __shared__ uint2 sp[2][PT1];

    {   // W stage once per block (consumed after first in-loop sync)
        const float4* src = reinterpret_cast<const float4*>(g_wq1 + (size_t)k * WK1);
        float4* dst = reinterpret_cast<float4*>(swq);
        for (int i = t; i < WK1 / 4; i += 256) dst[i] = src[i];
    }

    const size_t kpair = (size_t)k * MAXP;
    const int gid = lane >> 2, tig = lane & 3;
    const int rbase = 32 * (wrp & 3);
    const int cbase = 32 * (wrp >> 2);
    const float2* wrow = swq + tig * SWQ;

    auto prefetch = [&](int tile, int b) {
        const int base = tile * PT1;
        const int r = t >> 1, half = t & 1;
        uint2 pr = (base + r < cnt) ? g_pairs[kpair + base + r]
                                    : make_uint2(0u, 0u);
        if (half == 0) sp[b][r] = pr;
        const float* src = feats + (size_t)pr.x * CIN + half * 16;
        float* dst = xb + ((size_t)b * PT1 + r) * SX1R + half * 16;
        cp_async16(dst,      src);
        cp_async16(dst + 4,  src + 4);
        cp_async16(dst + 8,  src + 8);
        cp_async16(dst + 12, src + 12);
    };

    prefetch(blockIdx.x, 0);
    CP_COMMIT();

    int buf = 0;
    for (int tile = blockIdx.x; tile * PT1 < cnt; tile += gridDim.x, buf ^= 1) {
        const int nv = min(PT1, cnt - tile * PT1);
        CP_WAIT0();
        __syncthreads();

        {   // launch next tile's gather under this tile's compute
            int ntile = tile + gridDim.x;
            if (ntile * PT1 < cnt) prefetch(ntile, buf ^ 1);
            CP_COMMIT();
        }

        const float* xr = xb + (size_t)buf * PT1 * SX1R;
        float4 acc[2][4];
#pragma unroll
        for (int mt = 0; mt < 2; mt++)
#pragma unroll
            for (int nt = 0; nt < 4; nt++) acc[mt][nt] = make_float4(0.f, 0.f, 0.f, 0.f);

#pragma unroll
        for (int ks = 0; ks < 4; ks++) {
            const float* xrr = xr + (rbase + gid) * SX1R + ks * 8 + tig;
            unsigned a00 = f2tf(xrr[0]),             a01 = f2tf(xrr[8  * SX1R]);
            unsigned a02 = f2tf(xrr[4]),             a03 = f2tf(xrr[8  * SX1R + 4]);
            unsigned a10 = f2tf(xrr[16 * SX1R]),     a11 = f2tf(xrr[24 * SX1R]);
            unsigned a12 = f2tf(xrr[16 * SX1R + 4]), a13 = f2tf(xrr[24 * SX1R + 4]);
            const float2* wk = wrow + ks * 4 * SWQ;
#pragma unroll
            for (int nt = 0; nt < 4; nt++) {
                float2 b = wk[cbase + nt * 8 + gid];
                unsigned b0 = __float_as_uint(b.x), b1 = __float_as_uint(b.y);
                mma_tf32(acc[0][nt], a00, a01, a02, a03, b0, b1);
                mma_tf32(acc[1][nt], a10, a11, a12, a13, b0, b1);
            }
        }

        // scatter: permuted channels -> red.v4 straight from accumulators
#pragma unroll
        for (int mt = 0; mt < 2; mt++) {
            const int r0 = rbase + mt * 16 + gid;
#pragma unroll
            for (int q = 0; q < 2; q++) {
                const int cc = cbase + 16 * q + 4 * tig;
                if (r0 < nv)
                    red_add_v4(g_h + (size_t)sp[buf][r0].y * CMID + cc,
                               make_float4(acc[mt][2 * q].x,     acc[mt][2 * q].y,
                                           acc[mt][2 * q + 1].x, acc[mt][2 * q + 1].y));
                if (r0 + 8 < nv)
                    red_add_v4(g_h + (size_t)sp[buf][r0 + 8].y * CMID + cc,
                               make_float4(acc[mt][2 * q].z,     acc[mt][2 * q].w,
                                           acc[mt][2 * q + 1].z, acc[mt][2 * q + 1].w));
            }
        }
    }
}

// ---------------------------------------------------------------------------
// Fused layer 2 (pipelined, PT=64): out[vout][0:32] += relu(h[vin][0:64])@W_out
// Warp tile MT=1 (rows 16*(w&3)), NT=2 (cols 16*(w>>2)). K=64 (8 ks).
// ---------------------------------------------------------------------------
__global__ __launch_bounds__(256) void fused2_kernel(float* __restrict__ out)
{
    const int k   = blockIdx.y;
    const int cnt = g_cnt[k];
    if (blockIdx.x * PT2 >= cnt) return;
    const int t    = threadIdx.x;
    const int lane = t & 31;
    const int wrp  = t >> 5;

    extern __shared__ float pool[];
    float*  xb  = pool;                                   // [2][PT2][SX2R]
    float2* swq = reinterpret_cast<float2*>(pool + 2 * PT2 * SX2R);
    __shared__ uint2 sp[2][PT2];

    {
        const float4* src = reinterpret_cast<const float4*>(g_wq2 + (size_t)k * WK2);
        float4* dst = reinterpret_cast<float4*>(swq);
        for (int i = t; i < WK2 / 4; i += 256) dst[i] = src[i];
    }

    const size_t kpair = (size_t)k * MAXP;
    const int gid = lane >> 2, tig = lane & 3;
    const int rbase = 16 * (wrp & 3);
    const int cbase = 16 * (wrp >> 2);
    const float2* wrow = swq + tig * SWQ;

    auto prefetch = [&](int tile, int b) {
        const int base = tile * PT2;
        const int r = t >> 2, q = t & 3;
        uint2 pr = (base + r < cnt) ? g_pairs[kpair + base + r]
                                    : make_uint2(0u, 0u);
        if (q == 0) sp[b][r] = pr;
        const float* src = g_h + (size_t)pr.x * CMID + q * 16;
        float* dst = xb + ((size_t)b * PT2 + r) * SX2R + q * 16;
        cp_async16(dst,      src);
        cp_async16(dst + 4,  src + 4);
        cp_async16(dst + 8,  src + 8);
        cp_async16(dst + 12, src + 12);
    };

    prefetch(blockIdx.x, 0);
    CP_COMMIT();

    int buf = 0;
    for (int tile = blockIdx.x; tile * PT2 < cnt; tile += gridDim.x, buf ^= 1) {
        const int nv = min(PT2, cnt - tile * PT2);
        CP_WAIT0();
        __syncthreads();

        {
            int ntile = tile + gridDim.x;
            if (ntile * PT2 < cnt) prefetch(ntile, buf ^ 1);
            CP_COMMIT();
        }

        const float* xr = xb + (size_t)buf * PT2 * SX2R;
        float4 acc[2];
        acc[0] = make_float4(0.f, 0.f, 0.f, 0.f);
        acc[1] = make_float4(0.f, 0.f, 0.f, 0.f);

#pragma unroll
        for (int ks = 0; ks < 8; ks++) {
            const float* xrr = xr + (rbase + gid) * SX2R + ks * 8 + tig;
            unsigned a0 = f2tf(fmaxf(xrr[0],            0.f));
            unsigned a1 = f2tf(fmaxf(xrr[8 * SX2R],     0.f));
            unsigned a2 = f2tf(fmaxf(xrr[4],            0.f));
            unsigned a3 = f2tf(fmaxf(xrr[8 * SX2R + 4], 0.f));
            const float2* wk = wrow + ks * 4 * SWQ;
#pragma unroll
            for (int nt = 0; nt < 2; nt++) {
                float2 b = wk[cbase + nt * 8 + gid];
                mma_tf32(acc[nt], a0, a1, a2, a3,
                         __float_as_uint(b.x), __float_as_uint(b.y));
            }
        }

        // scatter: permuted channels -> one red.v4 per row
        {
            const int r0 = rbase + gid;
            const int cc = cbase + 4 * tig;
            if (r0 < nv)
                red_add_v4(out + (size_t)sp[buf][r0].y * COUT + cc,
                           make_float4(acc[0].x, acc[0].y, acc[1].x, acc[1].y));
            if (r0 + 8 < nv)
                red_add_v4(out + (size_t)sp[buf][r0 + 8].y * COUT + cc,
                           make_float4(acc[0].z, acc[0].w, acc[1].z, acc[1].w));
        }
    }
}

// ---------------------------------------------------------------------------
// Inputs: feats f32[N,32], nbr_in_idx i32[K,P], nbr_out_idx i32[K,P],
// nbr_mask f32[K,P], W_in f32[K,32,64], W_out f32[K,64,32]. Output f32[N,32].
// ---------------------------------------------------------------------------
extern "C" void kernel_launch(void* const* d_in, const int* in_sizes, int n_in,
                              void* d_out, int out_size) {
    const float* feats   = (const float*)d_in[0];
    const int*   in_idx  = (const int*)  d_in[1];
    const int*   out_idx = (const int*)  d_in[2];
    const float* mask    = (const float*)d_in[3];
    const float* W_in    = (const float*)d_in[4];
    const float* W_out   = (const float*)d_in[5];
    float*       out     = (float*)      d_out;

    const int N = in_sizes[0] / CIN;
    const int K = in_sizes[4] / (CIN * CMID);
    const int P = in_sizes[3] / K;

    const int smem1 = POOL1F * (int)sizeof(float);   // ~45.6 KB
    const int smem2 = POOL2F * (int)sizeof(float);   // ~52.2 KB
    cudaFuncSetAttribute(fused1_kernel,
        cudaFuncAttributeMaxDynamicSharedMemorySize, smem1);
    cudaFuncSetAttribute(fused2_kernel,
        cudaFuncAttributeMaxDynamicSharedMemorySize, smem2);

    const int n_out4 = N * COUT / 4;
    const int n_h4   = N * CMID / 4;
    const int nmax   = (n_out4 > n_h4) ? n_out4 : n_h4;
    zero_kernel<<<(nmax + 255) / 256, 256>>>((float4*)out, n_out4, n_h4);

    const int wtot = K * CIN * CMID;
    wprep_kernel<<<(wtot + 255) / 256, 256>>>(W_in, W_out, K);

    dim3 gc((P + 255) / 256, K);
    compact_kernel<<<gc, 256>>>(in_idx, out_idx, mask, P);

    const int gx1 = (((P + PT1 - 1) / PT1) + 3) / 4;   // ~4 tiles per block
    const int gx2 = (((P + PT2 - 1) / PT2) + 7) / 8;   // ~8 tiles per block
    fused1_kernel<<<dim3(gx1, K), 256, smem1>>>(feats);
    fused2_kernel<<<dim3(gx2, K), 256, smem2>>>(out);
}